// round 10
// baseline (speedup 1.0000x reference)
#include <cuda_runtime.h>
#include <cuda_fp16.h>
#include <cstdint>
#include <cstddef>

// ---------------------------------------------------------------------------
// RyeElman, round 9 (= round 8 + eqh staging index fix).
// Warp-specialized single pre-GEMM phase:
//   warps 0-3  : Gram (row-per-lane, conflict-free transposed panel)
//   warps 4-15 : dense A staging (LDG.128 x4 -> permuted pack -> STS.128 x2)
//   warps 16-31: fragment table copy + bii/Wee
// GEMM/epilogue identical to round 7 (fp16 m16n8k16, smem fragment table).
// ---------------------------------------------------------------------------

#define BDIM  1024
#define ROWSB 128
#define KD    192
#define NPAIR 153
#define NKS   22
#define ASTR  360                // halves per A row (180 words; conflict-free)

#define TBL_STEP 1152
#define TBL_TOT  (NKS * TBL_STEP)            // 25344 uint32 = 101.4 KB
__device__ __align__(16) uint32_t d_WB[TBL_TOT];

// smem float offsets
#define SF_BII  0                  // 128
#define SF_WEE  128                // 272 -> 400
#define SF_GS   400                // 128*16 -> 2448
#define SF_ET   2448               // 4 warps * 51*33 = 6732 -> 9180
#define SF_TBL  9184               // 25344 uint32 (16B aligned)
#define SF_A    34528              // 128*360 halves = 23040 floats
#define SF_TOTAL (SF_A + ROWSB * ASTR / 2)   // 57568 floats = 230272 B
#define ETW (51 * 33)

__device__ __forceinline__ void mma_f16(float* c, uint32_t a0, uint32_t a1,
                                        uint32_t a2, uint32_t a3,
                                        uint32_t b0, uint32_t b1) {
    asm volatile(
        "mma.sync.aligned.m16n8k16.row.col.f32.f16.f16.f32 "
        "{%0,%1,%2,%3}, {%4,%5,%6,%7}, {%8,%9}, {%0,%1,%2,%3};"
        : "+f"(c[0]), "+f"(c[1]), "+f"(c[2]), "+f"(c[3])
        : "r"(a0), "r"(a1), "r"(a2), "r"(a3), "r"(b0), "r"(b1));
}

// pair-permuted A column layout (verified R5-R7)
__device__ __forceinline__ int pair_off(int k) {          // k even
    int group = k >> 4, p = (k >> 1) & 7;
    int ppos = ((p & 3) << 1) | (p >> 2);
    return group * 16 + ppos * 2;
}
__device__ __forceinline__ int elem_off(int k) {
    return pair_off(k & ~1) + (k & 1);
}

__device__ __forceinline__ float tanh_ap(float x) {
    float y;
    asm("tanh.approx.f32 %0, %1;" : "=f"(y) : "f"(x));
    return y;
}
__device__ __forceinline__ uint32_t packh2(float a, float b) {
    __half2 h = __floats2half2_rn(a, b);
    return *reinterpret_cast<uint32_t*>(&h);
}

// ---------------------------------------------------------------------------
// K0: trimmed fragment-major fp16 table (unchanged, verified).
// ---------------------------------------------------------------------------
__device__ __forceinline__ float wbig_val(int k, int n,
                                          const float* Wii, const float* Wdamp,
                                          const float* Wl,  const float* Wr) {
    if (k < KD) return (n < 128) ? Wii[k * 128 + n] : Wdamp[k * 16 + (n - 128)];
    if (k < KD + NPAIR && n < 128) {
        int p = k - KD, c = 0, rem = p;
        while (rem >= 17 - c) { rem -= 17 - c; c++; }
        int c2 = c + rem;
        float g = Wl[c * 128 + n] * Wr[c2 * 128 + n];
        if (c2 != c) g += Wl[c2 * 128 + n] * Wr[c * 128 + n];
        return g;
    }
    return 0.f;
}

__global__ void prep_w_kernel(const float* __restrict__ Wii,
                              const float* __restrict__ Wdamp,
                              const float* __restrict__ Wl,
                              const float* __restrict__ Wr) {
    int idx = blockIdx.x * blockDim.x + threadIdx.x;
    if (idx >= TBL_TOT) return;
    int t = idx / TBL_STEP, off = idx - t * TBL_STEP;
    int colW, lane, reg;
    if (off < 960) { colW = off / 320; int rm = off - colW * 320; lane = rm / 10; reg = rm - lane * 10; }
    else           { colW = 3;         int rm = off - 960;        lane = rm / 6;  reg = rm - lane * 6; }
    int tile = reg >> 1, bsel = reg & 1;
    int n = colW * 40 + tile * 8 + (lane >> 2);
    int k = t * 16 + 2 * (lane & 3) + bsel * 8;
    float v0 = wbig_val(k, n, Wii, Wdamp, Wl, Wr);
    float v1 = wbig_val(k + 1, n, Wii, Wdamp, Wl, Wr);
    d_WB[idx] = packh2(v0, v1);
}

// ---------------------------------------------------------------------------
// GEMM inner loop (k-step range [T0,T1)), all operands conflict-free LDS.
// ---------------------------------------------------------------------------
template<int NT, int T0, int T1>
__device__ __forceinline__ void do_gemm16(const __half* ArA, const __half* ArB,
                                          const uint32_t* Bp, float (*acc)[4]) {
#pragma unroll
    for (int t = T0; t < T1; t++) {
        uint2 aA = *reinterpret_cast<const uint2*>(ArA + t * 16);
        uint2 aB = *reinterpret_cast<const uint2*>(ArB + t * 16);
        const uint32_t* bp = Bp + t * TBL_STEP;
#pragma unroll
        for (int nt = 0; nt < NT; nt++) {
            uint2 b = *reinterpret_cast<const uint2*>(bp + 2 * nt);
            mma_f16(acc[nt], aA.x, aB.x, aA.y, aB.y, b.x, b.y);
        }
    }
}

// ---------------------------------------------------------------------------
// K1: fused main kernel.
// ---------------------------------------------------------------------------
__global__ __launch_bounds__(BDIM, 1)
void rye_main(const float* __restrict__ invi, const float* __restrict__ eqi,
              const float* __restrict__ invh, const float* __restrict__ eqh,
              const float* __restrict__ bii,  const float* __restrict__ Wee,
              float* __restrict__ out, int Btot) {
    extern __shared__ float smf[];
    __half*   As = reinterpret_cast<__half*>(smf + SF_A);
    uint32_t* Tb = reinterpret_cast<uint32_t*>(smf + SF_TBL);
    float*    Gs = smf + SF_GS;

    int tid = threadIdx.x, wid = tid >> 5, lane = tid & 31;
    size_t row0 = (size_t)blockIdx.x * ROWSB;

    // ==================== single pre-GEMM phase (warp-specialized) ==========
    if (wid < 4) {
        // ---- Gram warps: rows rbase..rbase+31, lane = row ----
        float* Et = smf + SF_ET + wid * ETW;       // [s*17+cc][row], stride 33
        int rbase = wid * 32;
        // pass 1: transposed staging (coalesced LDG, scatter STS stride 33)
        for (int j4 = lane; j4 < 384; j4 += 32) {   // eqh: 32 rows * 12 float4
            int row = j4 / 12, q4 = j4 - row * 12;
            int s = q4 >> 2, cb = (q4 & 3) * 4;
            // row layout [s(3), c(16)] -> float4 index within row is q4 itself
            float4 v = reinterpret_cast<const float4*>(eqh + (row0 + rbase + row) * 48)[q4];
            float* base = Et + (s * 17 + 1 + cb) * 33 + row;
            base[0] = v.x; base[33] = v.y; base[66] = v.z; base[99] = v.w;
        }
        for (int j = lane; j < 96; j += 32) {       // eqi: 32 rows * 3
            int row = j / 3, s = j - row * 3;
            Et[(s * 17) * 33 + row] = eqi[(row0 + rbase) * 3 + j];
        }
        __syncwarp();
        // pass 2: f = e * invn, in place (lane-uniform addressing)
#pragma unroll
        for (int c = 0; c < 17; c++) {
            float e0 = Et[c * 33 + lane];
            float e1 = Et[(17 + c) * 33 + lane];
            float e2 = Et[(34 + c) * 33 + lane];
            float ic = __frcp_rn(fmaf(e0, e0, fmaf(e1, e1, fmaf(e2, e2, 1e-6f))));
            Et[c * 33 + lane]        = e0 * ic;
            Et[(17 + c) * 33 + lane] = e1 * ic;
            Et[(34 + c) * 33 + lane] = e2 * ic;
        }
        __syncwarp();
        // pass 3: Mn entries -> A cols [192,345); zeros [345,352)
        __half* Ar = As + (rbase + lane) * ASTR;
#pragma unroll
        for (int c = 0; c < 16; c++) {
            float f0 = Et[c * 33 + lane];
            float f1 = Et[(17 + c) * 33 + lane];
            float f2 = Et[(34 + c) * 33 + lane];
            int pbase = c * 17 - (c * (c - 1)) / 2 - c;
            for (int c2 = c; c2 < 17; c2++) {
                float m = fmaf(f0, Et[c2 * 33 + lane],
                          fmaf(f1, Et[(17 + c2) * 33 + lane],
                               f2 * Et[(34 + c2) * 33 + lane]));
                Ar[elem_off(KD + pbase + c2)] = __float2half(m);
            }
        }
        {   // (16,16) entry (p=152, k=344) packed with zero pad at 345
            float f0 = Et[16 * 33 + lane], f1 = Et[33 * 33 + lane], f2 = Et[50 * 33 + lane];
            float m = fmaf(f0, f0, fmaf(f1, f1, f2 * f2));
            *reinterpret_cast<uint32_t*>(Ar + pair_off(344)) = packh2(m, 0.f);
            uint32_t z = 0;
            *reinterpret_cast<uint32_t*>(Ar + pair_off(346)) = z;
            *reinterpret_cast<uint32_t*>(Ar + pair_off(348)) = z;
            *reinterpret_cast<uint32_t*>(Ar + pair_off(350)) = z;
        }
    } else if (wid < 16) {
        // ---- A dense staging: 1536 (row, k-group) tasks over 384 threads ----
        int u = tid - 128;
        for (int task = u; task < ROWSB * 12; task += 384) {
            int r = task / 12, grp = task - r * 12;
            const float4* src = (grp < 4)
                ? reinterpret_cast<const float4*>(invi + (row0 + r) * 64)  + grp * 4
                : reinterpret_cast<const float4*>(invh + (row0 + r) * 128) + (grp - 4) * 4;
            float4 v0 = src[0], v1 = src[1], v2 = src[2], v3 = src[3];
            uint4 lo, hi;
            lo.x = packh2(v0.x, v0.y); lo.y = packh2(v2.x, v2.y);
            lo.z = packh2(v0.z, v0.w); lo.w = packh2(v2.z, v2.w);
            hi.x = packh2(v1.x, v1.y); hi.y = packh2(v3.x, v3.y);
            hi.z = packh2(v1.z, v1.w); hi.w = packh2(v3.z, v3.w);
            uint4* dst = reinterpret_cast<uint4*>(As + r * ASTR + grp * 16);
            dst[0] = lo; dst[1] = hi;
        }
    } else {
        // ---- table copy + consts ----
        int u = tid - 512;
        const uint4* src = reinterpret_cast<const uint4*>(d_WB);
        uint4* dst = reinterpret_cast<uint4*>(Tb);
        for (int i = u; i < TBL_TOT / 4; i += 512) dst[i] = src[i];
        if (u < 128) smf[SF_BII + u] = bii[u];
        if (u >= 128 && u < 400) smf[SF_WEE + u - 128] = Wee[u - 128];
    }
    __syncthreads();

    // ==================== GEMM + epilogue (R7-proven) =======================
    int mw = wid >> 2, colW = wid & 3;
    int m0 = mw * 16;
    int g = lane >> 2, t4 = lane & 3;
    const __half* ArA = As + (m0 + g) * ASTR + t4 * 4;
    const __half* ArB = ArA + 8 * ASTR;

    if (colW < 3) {
        const uint32_t* Bp = Tb + colW * 320 + lane * 10;
        float acc[5][4];
#pragma unroll
        for (int i = 0; i < 5; i++) acc[i][0] = acc[i][1] = acc[i][2] = acc[i][3] = 0.f;
        do_gemm16<5, 0, NKS>(ArA, ArB, Bp, acc);
        int lr = m0 + g;
        float* o0 = out + (row0 + lr) * 128;
        float* o1 = out + (row0 + lr + 8) * 128;
#pragma unroll
        for (int nt = 0; nt < 5; nt++) {
            int j = colW * 40 + nt * 8 + 2 * t4;
            float b0 = smf[SF_BII + j], b1 = smf[SF_BII + j + 1];
            float2 v0 = make_float2(tanh_ap(acc[nt][0] + b0), tanh_ap(acc[nt][1] + b1));
            float2 v1 = make_float2(tanh_ap(acc[nt][2] + b0), tanh_ap(acc[nt][3] + b1));
            *reinterpret_cast<float2*>(o0 + j) = v0;
            *reinterpret_cast<float2*>(o1 + j) = v1;
        }
    } else {
        const uint32_t* Bp = Tb + 960 + lane * 6;
        float acc[3][4];
#pragma unroll
        for (int i = 0; i < 3; i++) acc[i][0] = acc[i][1] = acc[i][2] = acc[i][3] = 0.f;
        do_gemm16<3, 0, 12>(ArA, ArB, Bp, acc);      // gate cols need k<192 only
        do_gemm16<1, 12, NKS>(ArA, ArB, Bp, acc);    // Gram rows: tanh tile only
        int lr = m0 + g;
        {   // nt=0 -> cols 120..127 (tanh)
            int j = 120 + 2 * t4;
            float b0 = smf[SF_BII + j], b1 = smf[SF_BII + j + 1];
            float2 v0 = make_float2(tanh_ap(acc[0][0] + b0), tanh_ap(acc[0][1] + b1));
            float2 v1 = make_float2(tanh_ap(acc[0][2] + b0), tanh_ap(acc[0][3] + b1));
            *reinterpret_cast<float2*>(out + (row0 + lr) * 128 + j)     = v0;
            *reinterpret_cast<float2*>(out + (row0 + lr + 8) * 128 + j) = v1;
        }
#pragma unroll
        for (int nt = 1; nt < 3; nt++) {             // gate cols 128..143
            int jc = (nt - 1) * 8 + 2 * t4;
            Gs[lr * 16 + jc]           = acc[nt][0];
            Gs[lr * 16 + jc + 1]       = acc[nt][1];
            Gs[(lr + 8) * 16 + jc]     = acc[nt][2];
            Gs[(lr + 8) * 16 + jc + 1] = acc[nt][3];
        }
    }
    __syncthreads();

    // ---- new_equivariant: one thread per (row, s), eq data from L2 ----
    if (tid < ROWSB * 3) {
        int r = tid / 3, s = tid - r * 3;
        size_t row = row0 + r;
        const float* Wee_s = smf + SF_WEE;
        float E[17];
        E[0] = eqi[row * 3 + s];
        const float4* eh = reinterpret_cast<const float4*>(eqh + row * 48 + s * 16);
#pragma unroll
        for (int q = 0; q < 4; q++) {
            float4 v = eh[q];
            E[1 + q * 4] = v.x; E[2 + q * 4] = v.y; E[3 + q * 4] = v.z; E[4 + q * 4] = v.w;
        }
        float4 res[4];
        float* rf = reinterpret_cast<float*>(res);
#pragma unroll
        for (int c = 0; c < 16; c++) {
            float sum = 0.f;
#pragma unroll
            for (int cc = 0; cc < 17; cc++) sum = fmaf(E[cc], Wee_s[cc * 16 + c], sum);
            rf[c] = fmaf(E[1 + c], Gs[r * 16 + c], sum);
        }
        float4* dst = reinterpret_cast<float4*>(out + (size_t)Btot * 128 + row * 48 + s * 16);
        dst[0] = res[0]; dst[1] = res[1]; dst[2] = res[2]; dst[3] = res[3];
    }
}

// ---------------------------------------------------------------------------
extern "C" void kernel_launch(void* const* d_in, const int* in_sizes, int n_in,
                              void* d_out, int out_size) {
    const float* invi  = (const float*)d_in[0];
    const float* eqi   = (const float*)d_in[1];
    const float* invh  = (const float*)d_in[2];
    const float* eqhid = (const float*)d_in[3];
    const float* Wl    = (const float*)d_in[4];
    const float* Wr    = (const float*)d_in[5];
    const float* Wii   = (const float*)d_in[6];
    const float* bii   = (const float*)d_in[7];
    const float* Wee   = (const float*)d_in[8];
    const float* Wdamp = (const float*)d_in[9];
    float* out = (float*)d_out;

    int Btot = in_sizes[0] / 64;

    prep_w_kernel<<<(TBL_TOT + 255) / 256, 256>>>(Wii, Wdamp, Wl, Wr);

    int smem_bytes = SF_TOTAL * 4;   // 230272 B
    cudaFuncSetAttribute(rye_main, cudaFuncAttributeMaxDynamicSharedMemorySize, smem_bytes);
    rye_main<<<Btot / ROWSB, BDIM, smem_bytes>>>(invi, eqi, invh, eqhid,
                                                 bii, Wee, out, Btot);
}

// round 12
// speedup vs baseline: 1.2288x; 1.2288x over previous
#include <cuda_runtime.h>
#include <cuda_fp16.h>
#include <cstdint>
#include <cstddef>

// ---------------------------------------------------------------------------
// RyeElman, round 11: 2 blocks/SM co-residency (round 10 + alignment fix:
// all global-table fetches are uint2 — per-lane offsets are only 8B-aligned).
//   BDIM=512, 64 rows/block, 16 warps = 4(M) x 4(N), m16/warp.
//   B fragment table read from GLOBAL (L1-resident, 101KB); A panel in smem
//   (conflict-free ASTR=360); distributed Gram (4 rows/warp, R7-proven).
// ---------------------------------------------------------------------------

#define BDIM  512
#define ROWSB 64
#define KD    192
#define NPAIR 153
#define NKS   22
#define ASTR  360                // halves per A row (180 words; conflict-free)

#define TBL_STEP 1152
#define TBL_TOT  (NKS * TBL_STEP)            // 25344 uint32 = 101.4 KB
__device__ __align__(16) uint32_t d_WB[TBL_TOT];

// smem float offsets
#define SF_BII  0                  // 128
#define SF_WEE  128                // 272 -> 400
#define SF_SLOT 400                // 16 warps * 272 = 4352 (Gram); Gs alias (1024)
#define SF_A    4752               // 64*360 halves = 11520 floats (byte 19008)
#define SF_TOTAL (SF_A + ROWSB * ASTR / 2)   // 16272 floats = 65088 B

__device__ __forceinline__ void mma_f16(float* c, uint32_t a0, uint32_t a1,
                                        uint32_t a2, uint32_t a3,
                                        uint32_t b0, uint32_t b1) {
    asm volatile(
        "mma.sync.aligned.m16n8k16.row.col.f32.f16.f16.f32 "
        "{%0,%1,%2,%3}, {%4,%5,%6,%7}, {%8,%9}, {%0,%1,%2,%3};"
        : "+f"(c[0]), "+f"(c[1]), "+f"(c[2]), "+f"(c[3])
        : "r"(a0), "r"(a1), "r"(a2), "r"(a3), "r"(b0), "r"(b1));
}

// pair-permuted A column layout (verified R5-R9)
__device__ __forceinline__ int pair_off(int k) {          // k even
    int group = k >> 4, p = (k >> 1) & 7;
    int ppos = ((p & 3) << 1) | (p >> 2);
    return group * 16 + ppos * 2;
}
__device__ __forceinline__ int elem_off(int k) {
    return pair_off(k & ~1) + (k & 1);
}

__device__ __forceinline__ float tanh_ap(float x) {
    float y;
    asm("tanh.approx.f32 %0, %1;" : "=f"(y) : "f"(x));
    return y;
}
__device__ __forceinline__ uint32_t packh2(float a, float b) {
    __half2 h = __floats2half2_rn(a, b);
    return *reinterpret_cast<uint32_t*>(&h);
}

// ---------------------------------------------------------------------------
// K0: trimmed fragment-major fp16 table (unchanged, verified).
// ---------------------------------------------------------------------------
__device__ __forceinline__ float wbig_val(int k, int n,
                                          const float* Wii, const float* Wdamp,
                                          const float* Wl,  const float* Wr) {
    if (k < KD) return (n < 128) ? Wii[k * 128 + n] : Wdamp[k * 16 + (n - 128)];
    if (k < KD + NPAIR && n < 128) {
        int p = k - KD, c = 0, rem = p;
        while (rem >= 17 - c) { rem -= 17 - c; c++; }
        int c2 = c + rem;
        float g = Wl[c * 128 + n] * Wr[c2 * 128 + n];
        if (c2 != c) g += Wl[c2 * 128 + n] * Wr[c * 128 + n];
        return g;
    }
    return 0.f;
}

__global__ void prep_w_kernel(const float* __restrict__ Wii,
                              const float* __restrict__ Wdamp,
                              const float* __restrict__ Wl,
                              const float* __restrict__ Wr) {
    int idx = blockIdx.x * blockDim.x + threadIdx.x;
    if (idx >= TBL_TOT) return;
    int t = idx / TBL_STEP, off = idx - t * TBL_STEP;
    int colW, lane, reg;
    if (off < 960) { colW = off / 320; int rm = off - colW * 320; lane = rm / 10; reg = rm - lane * 10; }
    else           { colW = 3;         int rm = off - 960;        lane = rm / 6;  reg = rm - lane * 6; }
    int tile = reg >> 1, bsel = reg & 1;
    int n = colW * 40 + tile * 8 + (lane >> 2);
    int k = t * 16 + 2 * (lane & 3) + bsel * 8;
    float v0 = wbig_val(k, n, Wii, Wdamp, Wl, Wr);
    float v1 = wbig_val(k + 1, n, Wii, Wdamp, Wl, Wr);
    d_WB[idx] = packh2(v0, v1);
}

// ---------------------------------------------------------------------------
// K1: fused main kernel. 512 threads / 64 rows / 2 blocks per SM.
// ---------------------------------------------------------------------------
__global__ __launch_bounds__(BDIM, 2)
void rye_main(const float* __restrict__ invi, const float* __restrict__ eqi,
              const float* __restrict__ invh, const float* __restrict__ eqh,
              const float* __restrict__ bii,  const float* __restrict__ Wee,
              float* __restrict__ out, int Btot) {
    extern __shared__ float smf[];
    __half* As = reinterpret_cast<__half*>(smf + SF_A);
    float*  Gs = smf + SF_SLOT;                 // alias of Gram slots, post-GEMM

    int tid = threadIdx.x, wid = tid >> 5, lane = tid & 31;
    size_t row0 = (size_t)blockIdx.x * ROWSB;

    // ==================== pre-GEMM phase (single barrier) ===================
    // ---- A dense staging: 768 (row, k-group) tasks over 512 threads ----
    for (int task = tid; task < ROWSB * 12; task += BDIM) {
        int r = task / 12, grp = task - r * 12;
        const float4* src = (grp < 4)
            ? reinterpret_cast<const float4*>(invi + (row0 + r) * 64)  + grp * 4
            : reinterpret_cast<const float4*>(invh + (row0 + r) * 128) + (grp - 4) * 4;
        float4 v0 = src[0], v1 = src[1], v2 = src[2], v3 = src[3];
        uint4 lo, hi;
        lo.x = packh2(v0.x, v0.y); lo.y = packh2(v2.x, v2.y);
        lo.z = packh2(v0.z, v0.w); lo.w = packh2(v2.z, v2.w);
        hi.x = packh2(v1.x, v1.y); hi.y = packh2(v3.x, v3.y);
        hi.z = packh2(v1.z, v1.w); hi.w = packh2(v3.z, v3.w);
        uint4* dst = reinterpret_cast<uint4*>(As + r * ASTR + grp * 16);
        dst[0] = lo; dst[1] = hi;
    }
    if (tid < 128) smf[SF_BII + tid] = bii[tid];
    if (tid >= 128 && tid < 400) smf[SF_WEE + tid - 128] = Wee[tid - 128];

    // ---- Gram (distributed, R7-proven): each warp 4 rows via private slot ---
    {
        float* slot = smf + SF_SLOT + wid * 272;             // 4 rows x 68 floats
        int rbase = wid * 4;
        for (int j = lane; j < 192; j += 32) {               // eqh, coalesced
            int d = j / 48, q = j - d * 48;
            int s = q >> 4, c = q & 15;
            slot[d * 68 + s * 17 + 1 + c] = eqh[(row0 + rbase) * 48 + j];
        }
        if (lane < 12) {                                     // eqi
            int d = lane / 3, s = lane - d * 3;
            slot[d * 68 + s * 17] = eqi[(row0 + rbase) * 3 + lane];
        }
        __syncwarp();
        for (int j = lane; j < 68; j += 32) {                // 1/norm
            int d = j / 17, c = j - d * 17;
            float* S = slot + d * 68;
            float e0 = S[c], e1 = S[17 + c], e2 = S[34 + c];
            S[51 + c] = __frcp_rn(fmaf(e0, e0, fmaf(e1, e1, fmaf(e2, e2, 1e-6f))));
        }
        __syncwarp();
        {
            int d = lane >> 3, sub = lane & 7;
            const float* S  = slot + d * 68;
            const float* IN = S + 51;
            __half* Ar = As + (rbase + d) * ASTR;
#pragma unroll
            for (int cs = 0; cs < 2; cs++) {
                int c = sub + cs * 8;
                float e0 = S[c], e1 = S[17 + c], e2 = S[34 + c];
                float ic = IN[c];
                int pbase = c * 17 - (c * (c - 1)) / 2 - c;
                for (int c2 = c; c2 < 17; c2++) {
                    float g = fmaf(e0, S[c2], fmaf(e1, S[17 + c2], e2 * S[34 + c2]));
                    Ar[elem_off(KD + pbase + c2)] = __float2half(g * ic * IN[c2]);
                }
            }
            if (sub == 0) {                                  // (16,16) + zero k pad
                float g = fmaf(S[16], S[16], fmaf(S[33], S[33], S[50] * S[50]));
                *reinterpret_cast<uint32_t*>(Ar + pair_off(344)) =
                    packh2(g * IN[16] * IN[16], 0.f);
                *reinterpret_cast<uint32_t*>(Ar + pair_off(346)) = 0u;
                *reinterpret_cast<uint32_t*>(Ar + pair_off(348)) = 0u;
                *reinterpret_cast<uint32_t*>(Ar + pair_off(350)) = 0u;
            }
        }
    }
    __syncthreads();

    // ==================== GEMM (B from global via uint2, L1-resident) =======
    int mw = wid >> 2, colW = wid & 3;
    int m0 = mw * 16;
    int g = lane >> 2, t4 = lane & 3;
    const __half* ArA = As + (m0 + g) * ASTR + t4 * 4;
    const __half* ArB = ArA + 8 * ASTR;

    if (colW < 3) {
        const uint32_t* Bp = d_WB + colW * 320 + lane * 10;  // even word -> 8B aligned
        float acc[5][4];
#pragma unroll
        for (int i = 0; i < 5; i++) acc[i][0] = acc[i][1] = acc[i][2] = acc[i][3] = 0.f;
        uint2 f[5];
#pragma unroll
        for (int i = 0; i < 5; i++) f[i] = *reinterpret_cast<const uint2*>(Bp + 2 * i);
#pragma unroll
        for (int t = 0; t < NKS; t++) {
            uint2 b[5];
#pragma unroll
            for (int i = 0; i < 5; i++) b[i] = f[i];
            if (t + 1 < NKS) {
                const uint32_t* p = Bp + (t + 1) * TBL_STEP;
#pragma unroll
                for (int i = 0; i < 5; i++) f[i] = *reinterpret_cast<const uint2*>(p + 2 * i);
            }
            uint2 aA = *reinterpret_cast<const uint2*>(ArA + t * 16);
            uint2 aB = *reinterpret_cast<const uint2*>(ArB + t * 16);
#pragma unroll
            for (int nt = 0; nt < 5; nt++)
                mma_f16(acc[nt], aA.x, aB.x, aA.y, aB.y, b[nt].x, b[nt].y);
        }
        int lr = m0 + g;
        float* o0 = out + (row0 + lr) * 128;
        float* o1 = out + (row0 + lr + 8) * 128;
#pragma unroll
        for (int nt = 0; nt < 5; nt++) {
            int j = colW * 40 + nt * 8 + 2 * t4;
            float b0 = smf[SF_BII + j], b1 = smf[SF_BII + j + 1];
            float2 v0 = make_float2(tanh_ap(acc[nt][0] + b0), tanh_ap(acc[nt][1] + b1));
            float2 v1 = make_float2(tanh_ap(acc[nt][2] + b0), tanh_ap(acc[nt][3] + b1));
            *reinterpret_cast<float2*>(o0 + j) = v0;
            *reinterpret_cast<float2*>(o1 + j) = v1;
        }
    } else {
        const uint32_t* Bp = d_WB + 960 + lane * 6;          // even word -> 8B aligned
        float acc[3][4];
#pragma unroll
        for (int i = 0; i < 3; i++) acc[i][0] = acc[i][1] = acc[i][2] = acc[i][3] = 0.f;
#pragma unroll
        for (int t = 0; t < 12; t++) {                       // gate cols: k<192 only
            const uint32_t* p = Bp + t * TBL_STEP;
            uint2 b0 = *reinterpret_cast<const uint2*>(p);
            uint2 b1 = *reinterpret_cast<const uint2*>(p + 2);
            uint2 b2 = *reinterpret_cast<const uint2*>(p + 4);
            uint2 aA = *reinterpret_cast<const uint2*>(ArA + t * 16);
            uint2 aB = *reinterpret_cast<const uint2*>(ArB + t * 16);
            mma_f16(acc[0], aA.x, aB.x, aA.y, aB.y, b0.x, b0.y);
            mma_f16(acc[1], aA.x, aB.x, aA.y, aB.y, b1.x, b1.y);
            mma_f16(acc[2], aA.x, aB.x, aA.y, aB.y, b2.x, b2.y);
        }
#pragma unroll
        for (int t = 12; t < NKS; t++) {                     // tanh tile only
            uint2 b0 = *reinterpret_cast<const uint2*>(Bp + t * TBL_STEP);
            uint2 aA = *reinterpret_cast<const uint2*>(ArA + t * 16);
            uint2 aB = *reinterpret_cast<const uint2*>(ArB + t * 16);
            mma_f16(acc[0], aA.x, aB.x, aA.y, aB.y, b0.x, b0.y);
        }
        int lr = m0 + g;
        {   // nt=0 -> cols 120..127 (tanh)
            int j = 120 + 2 * t4;
            float b0 = smf[SF_BII + j], b1 = smf[SF_BII + j + 1];
            float2 v0 = make_float2(tanh_ap(acc[0][0] + b0), tanh_ap(acc[0][1] + b1));
            float2 v1 = make_float2(tanh_ap(acc[0][2] + b0), tanh_ap(acc[0][3] + b1));
            *reinterpret_cast<float2*>(out + (row0 + lr) * 128 + j)     = v0;
            *reinterpret_cast<float2*>(out + (row0 + lr + 8) * 128 + j) = v1;
        }
#pragma unroll
        for (int nt = 1; nt < 3; nt++) {                     // gate cols 128..143
            int jc = (nt - 1) * 8 + 2 * t4;
            Gs[lr * 16 + jc]           = acc[nt][0];
            Gs[lr * 16 + jc + 1]       = acc[nt][1];
            Gs[(lr + 8) * 16 + jc]     = acc[nt][2];
            Gs[(lr + 8) * 16 + jc + 1] = acc[nt][3];
        }
    }
    __syncthreads();

    // ---- new_equivariant: one thread per (row, s), eq data from L2 ----
    if (tid < ROWSB * 3) {
        int r = tid / 3, s = tid - r * 3;
        size_t row = row0 + r;
        const float* Wee_s = smf + SF_WEE;
        float E[17];
        E[0] = eqi[row * 3 + s];
        const float4* eh = reinterpret_cast<const float4*>(eqh + row * 48 + s * 16);
#pragma unroll
        for (int q = 0; q < 4; q++) {
            float4 v = eh[q];
            E[1 + q * 4] = v.x; E[2 + q * 4] = v.y; E[3 + q * 4] = v.z; E[4 + q * 4] = v.w;
        }
        float4 res[4];
        float* rf = reinterpret_cast<float*>(res);
#pragma unroll
        for (int c = 0; c < 16; c++) {
            float sum = 0.f;
#pragma unroll
            for (int cc = 0; cc < 17; cc++) sum = fmaf(E[cc], Wee_s[cc * 16 + c], sum);
            rf[c] = fmaf(E[1 + c], Gs[r * 16 + c], sum);
        }
        float4* dst = reinterpret_cast<float4*>(out + (size_t)Btot * 128 + row * 48 + s * 16);
        dst[0] = res[0]; dst[1] = res[1]; dst[2] = res[2]; dst[3] = res[3];
    }
}

// ---------------------------------------------------------------------------
extern "C" void kernel_launch(void* const* d_in, const int* in_sizes, int n_in,
                              void* d_out, int out_size) {
    const float* invi  = (const float*)d_in[0];
    const float* eqi   = (const float*)d_in[1];
    const float* invh  = (const float*)d_in[2];
    const float* eqhid = (const float*)d_in[3];
    const float* Wl    = (const float*)d_in[4];
    const float* Wr    = (const float*)d_in[5];
    const float* Wii   = (const float*)d_in[6];
    const float* bii   = (const float*)d_in[7];
    const float* Wee   = (const float*)d_in[8];
    const float* Wdamp = (const float*)d_in[9];
    float* out = (float*)d_out;

    int Btot = in_sizes[0] / 64;

    prep_w_kernel<<<(TBL_TOT + 255) / 256, 256>>>(Wii, Wdamp, Wl, Wr);

    int smem_bytes = SF_TOTAL * 4;   // 65088 B -> 2 blocks/SM
    cudaFuncSetAttribute(rye_main, cudaFuncAttributeMaxDynamicSharedMemorySize, smem_bytes);
    rye_main<<<Btot / ROWSB, BDIM, smem_bytes>>>(invi, eqi, invh, eqhid,
                                                 bii, Wee, out, Btot);
}

// round 13
// speedup vs baseline: 1.3391x; 1.0898x over previous
#include <cuda_runtime.h>
#include <cuda_fp16.h>
#include <cstdint>
#include <cstddef>

// ---------------------------------------------------------------------------
// RyeElman, round 12: = round 11 + coalesced fragment-table layout.
//   Table layout now [k][colW][pair][lane]: per-lane uint2 at lane*2 words,
//   so each B fetch is a fully coalesced 256B request (2 wavefronts vs 10).
//   BDIM=512, 64 rows/block, 2 blocks/SM; 16 warps = 4(M) x 4(N), m16/warp.
// ---------------------------------------------------------------------------

#define BDIM  512
#define ROWSB 64
#define KD    192
#define NPAIR 153
#define NKS   22
#define ASTR  360                // halves per A row (180 words; conflict-free)

#define TBL_STEP 1152
#define TBL_TOT  (NKS * TBL_STEP)            // 25344 uint32 = 101.4 KB
__device__ __align__(16) uint32_t d_WB[TBL_TOT];

// smem float offsets
#define SF_BII  0                  // 128
#define SF_WEE  128                // 272 -> 400
#define SF_SLOT 400                // 16 warps * 272 = 4352 (Gram); Gs alias (1024)
#define SF_A    4752               // 64*360 halves = 11520 floats
#define SF_TOTAL (SF_A + ROWSB * ASTR / 2)   // 16272 floats = 65088 B

__device__ __forceinline__ void mma_f16(float* c, uint32_t a0, uint32_t a1,
                                        uint32_t a2, uint32_t a3,
                                        uint32_t b0, uint32_t b1) {
    asm volatile(
        "mma.sync.aligned.m16n8k16.row.col.f32.f16.f16.f32 "
        "{%0,%1,%2,%3}, {%4,%5,%6,%7}, {%8,%9}, {%0,%1,%2,%3};"
        : "+f"(c[0]), "+f"(c[1]), "+f"(c[2]), "+f"(c[3])
        : "r"(a0), "r"(a1), "r"(a2), "r"(a3), "r"(b0), "r"(b1));
}

// pair-permuted A column layout (verified R5-R11)
__device__ __forceinline__ int pair_off(int k) {          // k even
    int group = k >> 4, p = (k >> 1) & 7;
    int ppos = ((p & 3) << 1) | (p >> 2);
    return group * 16 + ppos * 2;
}
__device__ __forceinline__ int elem_off(int k) {
    return pair_off(k & ~1) + (k & 1);
}

__device__ __forceinline__ float tanh_ap(float x) {
    float y;
    asm("tanh.approx.f32 %0, %1;" : "=f"(y) : "f"(x));
    return y;
}
__device__ __forceinline__ uint32_t packh2(float a, float b) {
    __half2 h = __floats2half2_rn(a, b);
    return *reinterpret_cast<uint32_t*>(&h);
}

// ---------------------------------------------------------------------------
// K0: fragment-major fp16 table, COALESCED layout [t][colW][pair i][lane][bsel].
//   word (t, colW, i, lane, bsel):
//     colW<3 : off = colW*320 + i*64 + lane*2 + bsel          (i = 0..4)
//     colW==3: off = 960      + i*64 + lane*2 + bsel          (i = 0..2)
//   value  = half2( Wbig(k, n), Wbig(k+1, n) )
//     n = colW*40 + i*8 + (lane>>2),  k = t*16 + 2*(lane&3) + bsel*8
// ---------------------------------------------------------------------------
__device__ __forceinline__ float wbig_val(int k, int n,
                                          const float* Wii, const float* Wdamp,
                                          const float* Wl,  const float* Wr) {
    if (k < KD) return (n < 128) ? Wii[k * 128 + n] : Wdamp[k * 16 + (n - 128)];
    if (k < KD + NPAIR && n < 128) {
        int p = k - KD, c = 0, rem = p;
        while (rem >= 17 - c) { rem -= 17 - c; c++; }
        int c2 = c + rem;
        float g = Wl[c * 128 + n] * Wr[c2 * 128 + n];
        if (c2 != c) g += Wl[c2 * 128 + n] * Wr[c * 128 + n];
        return g;
    }
    return 0.f;
}

__global__ void prep_w_kernel(const float* __restrict__ Wii,
                              const float* __restrict__ Wdamp,
                              const float* __restrict__ Wl,
                              const float* __restrict__ Wr) {
    int idx = blockIdx.x * blockDim.x + threadIdx.x;
    if (idx >= TBL_TOT) return;
    int t = idx / TBL_STEP, off = idx - t * TBL_STEP;
    int colW, i, w;
    if (off < 960) { colW = off / 320; int rm = off - colW * 320; i = rm >> 6; w = rm & 63; }
    else           { colW = 3;         int rm = off - 960;        i = rm >> 6; w = rm & 63; }
    int lane = w >> 1, bsel = w & 1;
    int n = colW * 40 + i * 8 + (lane >> 2);
    int k = t * 16 + 2 * (lane & 3) + bsel * 8;
    float v0 = wbig_val(k, n, Wii, Wdamp, Wl, Wr);
    float v1 = wbig_val(k + 1, n, Wii, Wdamp, Wl, Wr);
    d_WB[idx] = packh2(v0, v1);
}

// ---------------------------------------------------------------------------
// K1: fused main kernel. 512 threads / 64 rows / 2 blocks per SM.
// ---------------------------------------------------------------------------
__global__ __launch_bounds__(BDIM, 2)
void rye_main(const float* __restrict__ invi, const float* __restrict__ eqi,
              const float* __restrict__ invh, const float* __restrict__ eqh,
              const float* __restrict__ bii,  const float* __restrict__ Wee,
              float* __restrict__ out, int Btot) {
    extern __shared__ float smf[];
    __half* As = reinterpret_cast<__half*>(smf + SF_A);
    float*  Gs = smf + SF_SLOT;                 // alias of Gram slots, post-GEMM

    int tid = threadIdx.x, wid = tid >> 5, lane = tid & 31;
    size_t row0 = (size_t)blockIdx.x * ROWSB;

    // ==================== pre-GEMM phase (single barrier) ===================
    // ---- A dense staging: 768 (row, k-group) tasks over 512 threads ----
    for (int task = tid; task < ROWSB * 12; task += BDIM) {
        int r = task / 12, grp = task - r * 12;
        const float4* src = (grp < 4)
            ? reinterpret_cast<const float4*>(invi + (row0 + r) * 64)  + grp * 4
            : reinterpret_cast<const float4*>(invh + (row0 + r) * 128) + (grp - 4) * 4;
        float4 v0 = src[0], v1 = src[1], v2 = src[2], v3 = src[3];
        uint4 lo, hi;
        lo.x = packh2(v0.x, v0.y); lo.y = packh2(v2.x, v2.y);
        lo.z = packh2(v0.z, v0.w); lo.w = packh2(v2.z, v2.w);
        hi.x = packh2(v1.x, v1.y); hi.y = packh2(v3.x, v3.y);
        hi.z = packh2(v1.z, v1.w); hi.w = packh2(v3.z, v3.w);
        uint4* dst = reinterpret_cast<uint4*>(As + r * ASTR + grp * 16);
        dst[0] = lo; dst[1] = hi;
    }
    if (tid < 128) smf[SF_BII + tid] = bii[tid];
    if (tid >= 128 && tid < 400) smf[SF_WEE + tid - 128] = Wee[tid - 128];

    // ---- Gram (distributed, R7-proven): each warp 4 rows via private slot ---
    {
        float* slot = smf + SF_SLOT + wid * 272;             // 4 rows x 68 floats
        int rbase = wid * 4;
        for (int j = lane; j < 192; j += 32) {               // eqh, coalesced
            int d = j / 48, q = j - d * 48;
            int s = q >> 4, c = q & 15;
            slot[d * 68 + s * 17 + 1 + c] = eqh[(row0 + rbase) * 48 + j];
        }
        if (lane < 12) {                                     // eqi
            int d = lane / 3, s = lane - d * 3;
            slot[d * 68 + s * 17] = eqi[(row0 + rbase) * 3 + lane];
        }
        __syncwarp();
        for (int j = lane; j < 68; j += 32) {                // 1/norm
            int d = j / 17, c = j - d * 17;
            float* S = slot + d * 68;
            float e0 = S[c], e1 = S[17 + c], e2 = S[34 + c];
            S[51 + c] = __frcp_rn(fmaf(e0, e0, fmaf(e1, e1, fmaf(e2, e2, 1e-6f))));
        }
        __syncwarp();
        {
            int d = lane >> 3, sub = lane & 7;
            const float* S  = slot + d * 68;
            const float* IN = S + 51;
            __half* Ar = As + (rbase + d) * ASTR;
#pragma unroll
            for (int cs = 0; cs < 2; cs++) {
                int c = sub + cs * 8;
                float e0 = S[c], e1 = S[17 + c], e2 = S[34 + c];
                float ic = IN[c];
                int pbase = c * 17 - (c * (c - 1)) / 2 - c;
                for (int c2 = c; c2 < 17; c2++) {
                    float g = fmaf(e0, S[c2], fmaf(e1, S[17 + c2], e2 * S[34 + c2]));
                    Ar[elem_off(KD + pbase + c2)] = __float2half(g * ic * IN[c2]);
                }
            }
            if (sub == 0) {                                  // (16,16) + zero k pad
                float g = fmaf(S[16], S[16], fmaf(S[33], S[33], S[50] * S[50]));
                *reinterpret_cast<uint32_t*>(Ar + pair_off(344)) =
                    packh2(g * IN[16] * IN[16], 0.f);
                *reinterpret_cast<uint32_t*>(Ar + pair_off(346)) = 0u;
                *reinterpret_cast<uint32_t*>(Ar + pair_off(348)) = 0u;
                *reinterpret_cast<uint32_t*>(Ar + pair_off(350)) = 0u;
            }
        }
    }
    __syncthreads();

    // ==================== GEMM (B from global, coalesced uint2) =============
    int mw = wid >> 2, colW = wid & 3;
    int m0 = mw * 16;
    int g = lane >> 2, t4 = lane & 3;
    const __half* ArA = As + (m0 + g) * ASTR + t4 * 4;
    const __half* ArB = ArA + 8 * ASTR;

    if (colW < 3) {
        const uint32_t* Bp = d_WB + colW * 320 + lane * 2;   // coalesced base
        float acc[5][4];
#pragma unroll
        for (int i = 0; i < 5; i++) acc[i][0] = acc[i][1] = acc[i][2] = acc[i][3] = 0.f;
        uint2 f[5];
#pragma unroll
        for (int i = 0; i < 5; i++) f[i] = *reinterpret_cast<const uint2*>(Bp + i * 64);
#pragma unroll
        for (int t = 0; t < NKS; t++) {
            uint2 b[5];
#pragma unroll
            for (int i = 0; i < 5; i++) b[i] = f[i];
            if (t + 1 < NKS) {
                const uint32_t* p = Bp + (t + 1) * TBL_STEP;
#pragma unroll
                for (int i = 0; i < 5; i++) f[i] = *reinterpret_cast<const uint2*>(p + i * 64);
            }
            uint2 aA = *reinterpret_cast<const uint2*>(ArA + t * 16);
            uint2 aB = *reinterpret_cast<const uint2*>(ArB + t * 16);
#pragma unroll
            for (int nt = 0; nt < 5; nt++)
                mma_f16(acc[nt], aA.x, aB.x, aA.y, aB.y, b[nt].x, b[nt].y);
        }
        int lr = m0 + g;
        float* o0 = out + (row0 + lr) * 128;
        float* o1 = out + (row0 + lr + 8) * 128;
#pragma unroll
        for (int nt = 0; nt < 5; nt++) {
            int j = colW * 40 + nt * 8 + 2 * t4;
            float b0 = smf[SF_BII + j], b1 = smf[SF_BII + j + 1];
            float2 v0 = make_float2(tanh_ap(acc[nt][0] + b0), tanh_ap(acc[nt][1] + b1));
            float2 v1 = make_float2(tanh_ap(acc[nt][2] + b0), tanh_ap(acc[nt][3] + b1));
            *reinterpret_cast<float2*>(o0 + j) = v0;
            *reinterpret_cast<float2*>(o1 + j) = v1;
        }
    } else {
        const uint32_t* Bp = d_WB + 960 + lane * 2;          // coalesced base
        float acc[3][4];
#pragma unroll
        for (int i = 0; i < 3; i++) acc[i][0] = acc[i][1] = acc[i][2] = acc[i][3] = 0.f;
#pragma unroll
        for (int t = 0; t < 12; t++) {                       // gate cols: k<192 only
            const uint32_t* p = Bp + t * TBL_STEP;
            uint2 b0 = *reinterpret_cast<const uint2*>(p);
            uint2 b1 = *reinterpret_cast<const uint2*>(p + 64);
            uint2 b2 = *reinterpret_cast<const uint2*>(p + 128);
            uint2 aA = *reinterpret_cast<const uint2*>(ArA + t * 16);
            uint2 aB = *reinterpret_cast<const uint2*>(ArB + t * 16);
            mma_f16(acc[0], aA.x, aB.x, aA.y, aB.y, b0.x, b0.y);
            mma_f16(acc[1], aA.x, aB.x, aA.y, aB.y, b1.x, b1.y);
            mma_f16(acc[2], aA.x, aB.x, aA.y, aB.y, b2.x, b2.y);
        }
#pragma unroll
        for (int t = 12; t < NKS; t++) {                     // tanh tile only
            uint2 b0 = *reinterpret_cast<const uint2*>(Bp + t * TBL_STEP);
            uint2 aA = *reinterpret_cast<const uint2*>(ArA + t * 16);
            uint2 aB = *reinterpret_cast<const uint2*>(ArB + t * 16);
            mma_f16(acc[0], aA.x, aB.x, aA.y, aB.y, b0.x, b0.y);
        }
        int lr = m0 + g;
        {   // nt=0 -> cols 120..127 (tanh)
            int j = 120 + 2 * t4;
            float b0 = smf[SF_BII + j], b1 = smf[SF_BII + j + 1];
            float2 v0 = make_float2(tanh_ap(acc[0][0] + b0), tanh_ap(acc[0][1] + b1));
            float2 v1 = make_float2(tanh_ap(acc[0][2] + b0), tanh_ap(acc[0][3] + b1));
            *reinterpret_cast<float2*>(out + (row0 + lr) * 128 + j)     = v0;
            *reinterpret_cast<float2*>(out + (row0 + lr + 8) * 128 + j) = v1;
        }
#pragma unroll
        for (int nt = 1; nt < 3; nt++) {                     // gate cols 128..143
            int jc = (nt - 1) * 8 + 2 * t4;
            Gs[lr * 16 + jc]           = acc[nt][0];
            Gs[lr * 16 + jc + 1]       = acc[nt][1];
            Gs[(lr + 8) * 16 + jc]     = acc[nt][2];
            Gs[(lr + 8) * 16 + jc + 1] = acc[nt][3];
        }
    }
    __syncthreads();

    // ---- new_equivariant: one thread per (row, s), eq data from L2 ----
    if (tid < ROWSB * 3) {
        int r = tid / 3, s = tid - r * 3;
        size_t row = row0 + r;
        const float* Wee_s = smf + SF_WEE;
        float E[17];
        E[0] = eqi[row * 3 + s];
        const float4* eh = reinterpret_cast<const float4*>(eqh + row * 48 + s * 16);
#pragma unroll
        for (int q = 0; q < 4; q++) {
            float4 v = eh[q];
            E[1 + q * 4] = v.x; E[2 + q * 4] = v.y; E[3 + q * 4] = v.z; E[4 + q * 4] = v.w;
        }
        float4 res[4];
        float* rf = reinterpret_cast<float*>(res);
#pragma unroll
        for (int c = 0; c < 16; c++) {
            float sum = 0.f;
#pragma unroll
            for (int cc = 0; cc < 17; cc++) sum = fmaf(E[cc], Wee_s[cc * 16 + c], sum);
            rf[c] = fmaf(E[1 + c], Gs[r * 16 + c], sum);
        }
        float4* dst = reinterpret_cast<float4*>(out + (size_t)Btot * 128 + row * 48 + s * 16);
        dst[0] = res[0]; dst[1] = res[1]; dst[2] = res[2]; dst[3] = res[3];
    }
}

// ---------------------------------------------------------------------------
extern "C" void kernel_launch(void* const* d_in, const int* in_sizes, int n_in,
                              void* d_out, int out_size) {
    const float* invi  = (const float*)d_in[0];
    const float* eqi   = (const float*)d_in[1];
    const float* invh  = (const float*)d_in[2];
    const float* eqhid = (const float*)d_in[3];
    const float* Wl    = (const float*)d_in[4];
    const float* Wr    = (const float*)d_in[5];
    const float* Wii   = (const float*)d_in[6];
    const float* bii   = (const float*)d_in[7];
    const float* Wee   = (const float*)d_in[8];
    const float* Wdamp = (const float*)d_in[9];
    float* out = (float*)d_out;

    int Btot = in_sizes[0] / 64;

    prep_w_kernel<<<(TBL_TOT + 255) / 256, 256>>>(Wii, Wdamp, Wl, Wr);

    int smem_bytes = SF_TOTAL * 4;   // 65088 B -> 2 blocks/SM
    cudaFuncSetAttribute(rye_main, cudaFuncAttributeMaxDynamicSharedMemorySize, smem_bytes);
    rye_main<<<Btot / ROWSB, BDIM, smem_bytes>>>(invi, eqi, invh, eqhid,
                                                 bii, Wee, out, Btot);
}